// round 13
// baseline (speedup 1.0000x reference)
#include <cuda_runtime.h>

// Problem constants (fixed shapes for this problem instance)
#define NBOX   2048
#define NBATCH 16
#define AH     256
#define AW     256
#define GRID   1024  // 16 batches x 64 bands (4 rows per block)

__device__ float    g_partial[GRID];
__device__ unsigned g_count = 0;

// bce = max(l,0) - l*m + log1p(exp(-|l|)); softplus arg in (1,2] -> fast math safe
__device__ __forceinline__ float bce_elem(float l, unsigned mb) {
    float t  = __expf(-fabsf(l));
    float sp = __logf(1.0f + t);
    float z  = fmaxf(l, 0.0f) - (mb ? l : 0.0f);
    return z + sp;
}

// Release-ordered counter bump: orders this block's prior partial store at L2
// without a gpu-scope membar / L1 flush.
__device__ __forceinline__ unsigned atom_inc_release(unsigned* p) {
    unsigned prev;
    asm volatile("atom.add.release.gpu.global.u32 %0, [%1], 1;"
                 : "=r"(prev) : "l"(p) : "memory");
    return prev;
}

__global__ __launch_bounds__(256, 8)
void la_loss_kernel(const float* __restrict__ am,
                    const float* __restrict__ tgt,
                    float* __restrict__ out)
{
    const int tid   = threadIdx.x;
    const int blk   = blockIdx.x;
    const int batch = blk >> 6;        // 0..15
    const int band  = blk & 63;        // 0..63
    const int blo   = band << 2;       // first row of 4-row band

    // ---- Front-batched prefetch: this block's 1024 logits (4 rows x 256) ----
    const float4 v = ((const float4*)am)[(size_t)blk * 256 + tid];

    __shared__ unsigned s_mask[4 * 8];     // 4 rows x 256 bits
    __shared__ float    s_warp[8];
    __shared__ unsigned s_last;

    if (tid < 32) s_mask[tid] = 0u;

    // ---- Phase 0: sampled range-find on sorted bidx ----
    // samples[j] = bidx[8j]; j0 = #samples < b, j1 = #samples < b+1
    // => all batch-b boxes lie in [max(0, 8*j0-7), min(NBOX, 8*j1+1)).
    const float fb  = (float)batch;
    const float fb1 = (float)(batch + 1);
    const float sv  = tgt[(size_t)tid * 48];          // tgt[(tid*8)*6]
    const int j0 = __syncthreads_count(sv < fb);      // barrier also covers s_mask init
    const int j1 = __syncthreads_count(sv < fb1);
    const int lo = max(0, (j0 << 3) - 7);
    const int hi = min(NBOX, (j1 << 3) + 1);

    // ---- Phase 1: scan only the bracketed window; scatter this band's mask ----
    int has = 0;
    for (int i = lo + tid; i < hi; i += 256) {
        const float* t = tgt + (size_t)i * 6;
        if (t[0] == fb) {
            has = 1;
            float xc = t[2], yc = t[3], bw = t[4], bh = t[5];
            float x1 = 1024.0f * (xc - bw * 0.5f);
            float y1 = 1024.0f * (yc - bh * 0.5f);
            float x2 = 1024.0f * (xc + bw * 0.5f);
            float y2 = 1024.0f * (yc + bh * 0.5f);
            bool valid = (x1 <= 1024.0f) && (y1 <= 1024.0f) &&
                         (x2 <= 1024.0f) && (y2 <= 1024.0f);
            int X1 = max(0, (int)truncf(x1 * 0.25f));
            int Y1 = max(0, (int)truncf(y1 * 0.25f));
            int X2 = max(0, min(AW, (int)(ceilf(x2 * 0.25f) + 1.0f)));
            int Y2 = max(0, min(AH, (int)(ceilf(y2 * 0.25f) + 1.0f)));
            int y0  = max(Y1, blo);
            int y1i = min(Y2, blo + 4);
            if (valid && X2 > X1 && y0 < y1i) {
                int w0 = X1 >> 5;
                int w1 = (X2 - 1) >> 5;
                for (int w = w0; w <= w1; w++) {
                    int lob = X1 - (w << 5); lob = (lob < 0) ? 0 : lob;  // 0..31
                    int hib = X2 - (w << 5);                             // >=1
                    unsigned mh  = (hib >= 32) ? 0xFFFFFFFFu : ((1u << hib) - 1u);
                    unsigned msk = mh & ~((1u << lob) - 1u);
                    for (int y = y0; y < y1i; y++)
                        atomicOr(&s_mask[((y - blo) << 3) + w], msk);
                }
            }
        }
    }
    const int anyhas = __syncthreads_or(has);   // barrier + block-wide has_box

    // ---- Phase 2: BCE over prefetched logits (4 elems/thread) ----
    float sum;
    {
        int ty  = tid >> 6;                  // row in band (0..3)
        int col = (tid & 63) << 2;           // starting bit
        unsigned bits = s_mask[(ty << 3) + (col >> 5)] >> (col & 31);
        sum  = bce_elem(v.x,  bits       & 1u);
        sum += bce_elem(v.y, (bits >> 1) & 1u);
        sum += bce_elem(v.z, (bits >> 2) & 1u);
        sum += bce_elem(v.w, (bits >> 3) & 1u);
    }

    // ---- Phase 3: block reduce (fixed order), publish partial ----
    #pragma unroll
    for (int off = 16; off; off >>= 1)
        sum += __shfl_down_sync(0xFFFFFFFFu, sum, off);
    if ((tid & 31) == 0) s_warp[tid >> 5] = sum;
    __syncthreads();
    if (tid == 0) {
        float tot = 0.0f;
        #pragma unroll
        for (int w = 0; w < 8; w++) tot += s_warp[w];          // fixed order
        g_partial[blk] = anyhas ? tot * (1.0f / 65536.0f) : 0.0f;
        unsigned prev = atom_inc_release(&g_count);
        s_last = (prev == (unsigned)(gridDim.x - 1)) ? 1u : 0u;
    }
    __syncthreads();

    // ---- Phase 4: last block sums all partials in fixed order ----
    if (s_last) {
        __threadfence();   // single acquire-side fence, one block only
        volatile float* gp = g_partial;
        float t0 = (gp[tid]       + gp[tid + 256]) +
                   (gp[tid + 512] + gp[tid + 768]);
        #pragma unroll
        for (int off = 16; off; off >>= 1)
            t0 += __shfl_down_sync(0xFFFFFFFFu, t0, off);
        if ((tid & 31) == 0) s_warp[tid >> 5] = t0;
        __syncthreads();
        if (tid == 0) {
            float tot = 0.0f;
            #pragma unroll
            for (int w = 0; w < 8; w++) tot += s_warp[w];      // fixed order
            out[0]  = tot;
            g_count = 0u;   // reset for next graph replay
        }
    }
}

extern "C" void kernel_launch(void* const* d_in, const int* in_sizes, int n_in,
                              void* d_out, int out_size)
{
    const float* am  = (const float*)d_in[0];  // attention_mask (16,1,256,256) f32
    const float* tgt = (const float*)d_in[1];  // target (2048,6) f32
    (void)in_sizes; (void)n_in; (void)out_size;
    la_loss_kernel<<<GRID, 256>>>(am, tgt, (float*)d_out);
}